// round 16
// baseline (speedup 1.0000x reference)
#include <cuda_runtime.h>
#include <cuda_bf16.h>
#include <cstdint>
#include <math.h>

#define BATCH   32
#define NPATCH  196
#define NTOK    197
#define DIM     768
#define DFF     3072
#define NLAYER  12
#define NHEAD   12
#define HDIM    64
#define ROWS    (BATCH*NTOK)      // 6304
#define PROWS   (BATCH*NPATCH)    // 6272 = 49*128
#define MPAD    6400

// -------- device scratch (fp32 tf32-rounded, k-permuted) --------
__device__ float g_p[PROWS*DIM];
__device__ float g_cw[DIM*DIM];
__device__ float g_tok[ROWS*DIM];
__device__ float g_y[MPAD*DIM];
__device__ float g_qkv[ROWS*3*DIM];
__device__ float g_a[MPAD*DIM];
__device__ float g_f[MPAD*DFF];
__device__ float g_qkvT[NLAYER*3*DIM*DIM];
__device__ float g_projT[NLAYER*DIM*DIM];
__device__ float g_fc1T[(size_t)NLAYER*DFF*DIM];
__device__ float g_fc2T[(size_t)NLAYER*DIM*DFF];

// -------- helpers --------
__device__ __forceinline__ uint32_t smem_u32(const void* p) {
    uint32_t a;
    asm("{ .reg .u64 t; cvta.to.shared.u64 t, %1; cvt.u32.u64 %0, t; }" : "=r"(a) : "l"(p));
    return a;
}
__device__ __forceinline__ float rna(float x) {
    uint32_t u; asm("cvt.rna.tf32.f32 %0, %1;" : "=r"(u) : "f"(x));
    return __uint_as_float(u);
}
__device__ __host__ __forceinline__ int permk(int k) {
    return (k & ~15) | (((k & 3) << 2) | ((k & 15) >> 2));
}
#define CPA16(d, s) asm volatile("cp.async.cg.shared.global [%0], [%1], 16;" :: "r"(d), "l"(s))
#define CP_COMMIT() asm volatile("cp.async.commit_group;" ::: "memory")
#define CP_WAITG1() asm volatile("cp.async.wait_group 1;" ::: "memory")

__device__ __forceinline__ void lds128(uint32_t a, uint32_t* r) {
    asm volatile("ld.shared.v4.b32 {%0,%1,%2,%3}, [%4];"
                 : "=r"(r[0]), "=r"(r[1]), "=r"(r[2]), "=r"(r[3]) : "r"(a));
}
__device__ __forceinline__ void mma_tf32(float* c, uint32_t a0, uint32_t a1, uint32_t a2,
                                         uint32_t a3, uint32_t b0, uint32_t b1) {
    asm volatile("mma.sync.aligned.m16n8k8.row.col.f32.tf32.tf32.f32 "
        "{%0,%1,%2,%3}, {%4,%5,%6,%7}, {%8,%9}, {%0,%1,%2,%3};"
        : "+f"(c[0]), "+f"(c[1]), "+f"(c[2]), "+f"(c[3])
        : "r"(a0), "r"(a1), "r"(a2), "r"(a3), "r"(b0), "r"(b1));
}
__device__ __forceinline__ uint64_t pack2(float x, float y) {
    uint64_t r; asm("mov.b64 %0, {%1,%2};" : "=l"(r) : "f"(x), "f"(y)); return r;
}
__device__ __forceinline__ void unpack2(uint64_t v, float& x, float& y) {
    asm("mov.b64 {%0,%1}, %2;" : "=f"(x), "=f"(y) : "l"(v));
}
__device__ __forceinline__ void ffma2(uint64_t& d, uint64_t a, uint64_t b) {
    asm("fma.rn.f32x2 %0, %1, %2, %0;" : "+l"(d) : "l"(a), "l"(b));
}

// ------------------------------------------------------------
// tf32 GEMM: C = epi(A @ B^T); A[M][permK], B[N][permK] fp32.
// CTA 128x128, warp tile 32x64. k-chunk 32 stages (two 16-k
// sub-layouts), 3-stage cp.async, 96KB smem -> 2 CTAs/SM.
// NK2 = K/32 compile-time (24 or 96).
// ------------------------------------------------------------
#define F_BIAS 1
#define F_RES  2
#define F_GELU 4
#define F_PERM 8
#define F_EMB  16

#define ARR_F  8192                    // 128 rows * 64B (one 16-k sub-block, one matrix)
#define SUB_B  (2*ARR_F)               // 16384: A+B for one 16-k
#define STAGE_B (2*SUB_B)              // 32768: one 32-k chunk
#define GEMM_SMEM (3*STAGE_B)          // 98304 -> 2 CTAs/SM

template<int NK2>
__global__ __launch_bounds__(256, 2) void gemm_kernel(
    const float* __restrict__ A, const float* __restrict__ B,
    const float* __restrict__ bias, const float* __restrict__ res,
    float* __restrict__ Cf, int M, int N, int flags)
{
    constexpr int K = NK2 * 32;
    extern __shared__ char dsm[];
    const uint32_t sbase = smem_u32(dsm);
    const int tid = threadIdx.x, wid = tid >> 5, lane = tid & 31;
    const int bm = blockIdx.y * 128, bn = blockIdx.x * 128;
    const int warpM = wid & 3, warpN = wid >> 2;

    float acc[64];
    #pragma unroll
    for (int i = 0; i < 64; i++) acc[i] = 0.f;

    auto load_stage = [&](int j) {
        uint32_t sb = sbase + (uint32_t)(j % 3) * STAGE_B;
        int kb = j << 5;
        #pragma unroll
        for (int i = 0; i < 8; i++) {
            int slot = tid + i * 256;             // 2048 16B slots
            int mat = slot >> 10, rem = slot & 1023;
            int row = rem >> 3, seg = rem & 7;
            int sub = seg >> 2, s4 = seg & 3;
            const float* src = (mat ? B + (size_t)(bn + row) * K
                                    : A + (size_t)(bm + row) * K) + kb + sub * 16 + s4 * 4;
            uint32_t dst = sb + (uint32_t)sub * SUB_B + (uint32_t)mat * ARR_F
                         + (uint32_t)(row * 64 + s4 * 16);
            CPA16(dst, src);
        }
    };

    const int qrow = lane >> 2, qcol = (lane & 3) * 16;

    auto compute_stage = [&](int j) {
        uint32_t sb0 = sbase + (uint32_t)(j % 3) * STAGE_B;
        #pragma unroll
        for (int h2 = 0; h2 < 2; h2++) {
            uint32_t sb = sb0 + (uint32_t)h2 * SUB_B;
            uint32_t ax[2][4], ay[2][4], bb[8][4];
            #pragma unroll
            for (int m2 = 0; m2 < 2; m2++) {
                uint32_t r0 = warpM * 32 + m2 * 16 + qrow;
                lds128(sb + r0 * 64 + qcol, ax[m2]);
                lds128(sb + (r0 + 8) * 64 + qcol, ay[m2]);
            }
            #pragma unroll
            for (int p = 0; p < 8; p++) {
                uint32_t nrow = warpN * 64 + p * 8 + qrow;
                lds128(sb + ARR_F + nrow * 64 + qcol, bb[p]);
            }
            #pragma unroll
            for (int m2 = 0; m2 < 2; m2++)
                #pragma unroll
                for (int n8 = 0; n8 < 8; n8++)
                    mma_tf32(&acc[(m2 * 8 + n8) * 4],
                             ax[m2][0], ay[m2][0], ax[m2][1], ay[m2][1],
                             bb[n8][0], bb[n8][1]);
            #pragma unroll
            for (int m2 = 0; m2 < 2; m2++)
                #pragma unroll
                for (int n8 = 0; n8 < 8; n8++)
                    mma_tf32(&acc[(m2 * 8 + n8) * 4],
                             ax[m2][2], ay[m2][2], ax[m2][3], ay[m2][3],
                             bb[n8][2], bb[n8][3]);
        }
    };

    load_stage(0); CP_COMMIT();
    load_stage(1); CP_COMMIT();
    #pragma unroll 3
    for (int j = 0; j < NK2; j++) {
        CP_WAITG1();
        __syncthreads();
        if (j + 2 < NK2) load_stage(j + 2);
        CP_COMMIT();
        compute_stage(j);
    }

    // -------- epilogue --------
    #pragma unroll
    for (int m2 = 0; m2 < 2; m2++) {
        #pragma unroll
        for (int n8 = 0; n8 < 8; n8++) {
            float* c = &acc[(m2 * 8 + n8) * 4];
            int row0 = bm + warpM * 32 + m2 * 16 + (lane >> 2);
            int col  = bn + warpN * 64 + n8 * 8 + (lane & 3) * 2;
            #pragma unroll
            for (int h = 0; h < 2; h++) {
                int m = row0 + h * 8;
                if (m >= M) continue;
                float v0 = c[h * 2], v1 = c[h * 2 + 1];
                if (flags & F_BIAS) { v0 += bias[col]; v1 += bias[col + 1]; }
                if (flags & F_GELU) {
                    v0 = 0.5f * v0 * (1.0f + erff(v0 * 0.70710678118654752f));
                    v1 = 0.5f * v1 * (1.0f + erff(v1 * 0.70710678118654752f));
                }
                if (flags & F_EMB) {
                    int bb2 = m / NPATCH, nn = m % NPATCH;
                    float2 pv = *reinterpret_cast<const float2*>(&res[(size_t)(nn + 1) * N + col]);
                    v0 += pv.x; v1 += pv.y;
                    size_t oidx = (size_t)(bb2 * NTOK + nn + 1) * N + col;
                    float2 ov; ov.x = v0; ov.y = v1;
                    *reinterpret_cast<float2*>(&Cf[oidx]) = ov;
                    continue;
                }
                if (flags & F_PERM) {
                    size_t base = (size_t)m * N;
                    Cf[base + permk(col)]     = rna(v0);
                    Cf[base + permk(col + 1)] = rna(v1);
                    continue;
                }
                size_t idx = (size_t)m * N + col;
                if (flags & F_RES) {
                    float2 rv = *reinterpret_cast<const float2*>(&res[idx]);
                    v0 += rv.x; v1 += rv.y;
                }
                float2 ov; ov.x = v0; ov.y = v1;
                *reinterpret_cast<float2*>(&Cf[idx]) = ov;
            }
        }
    }
}

// ------------------------------------------------------------
// weight prep: transpose + rna + permute
// ------------------------------------------------------------
__device__ __forceinline__ void trans_tile(const float* __restrict__ in,
                                           float* __restrict__ outp,
                                           int K, int N, int kt, int nt)
{
    __shared__ float t[32][33];
    int n0 = nt * 32, k0 = kt * 32;
    int tx = threadIdx.x, ty = threadIdx.y;
    #pragma unroll
    for (int i = 0; i < 4; i++)
        t[ty + 8 * i][tx] = in[(size_t)(k0 + ty + 8 * i) * N + n0 + tx];
    __syncthreads();
    #pragma unroll
    for (int i = 0; i < 4; i++)
        outp[(size_t)(n0 + ty + 8 * i) * K + permk(k0 + tx)] = rna(t[tx][ty + 8 * i]);
}

__global__ void megaA_kernel(const float* __restrict__ qkv_w, const float* __restrict__ proj_w,
                             float* __restrict__ qT, float* __restrict__ pT)
{
    int layer = blockIdx.x / 2304, rr = blockIdx.x % 2304;
    if (rr < 1728)
        trans_tile(qkv_w + (size_t)layer * DIM * 3 * DIM,
                   qT + (size_t)layer * 3 * DIM * DIM, DIM, 3 * DIM, rr / 72, rr % 72);
    else {
        int r2 = rr - 1728;
        trans_tile(proj_w + (size_t)layer * DIM * DIM,
                   pT + (size_t)layer * DIM * DIM, DIM, DIM, r2 / 24, r2 % 24);
    }
}
__global__ void megaB_kernel(const float* __restrict__ fc1_w, const float* __restrict__ fc2_w,
                             float* __restrict__ f1T, float* __restrict__ f2T)
{
    int layer = blockIdx.x / 4608, rr = blockIdx.x % 4608;
    if (rr < 2304)
        trans_tile(fc1_w + (size_t)layer * DIM * DFF,
                   f1T + (size_t)layer * DFF * DIM, DIM, DFF, rr / 96, rr % 96);
    else {
        int r2 = rr - 2304;
        trans_tile(fc2_w + (size_t)layer * DFF * DIM,
                   f2T + (size_t)layer * DIM * DFF, DFF, DIM, r2 / 24, r2 % 24);
    }
}

__global__ void roundperm_kernel(const float* __restrict__ in, float* __restrict__ outp, int n)
{
    int idx = blockIdx.x * 256 + threadIdx.x;
    if (idx >= n) return;
    int row = idx / DIM, k = idx % DIM;
    outp[(size_t)row * DIM + permk(k)] = rna(in[idx]);
}
__global__ void im2col_kernel(const float* __restrict__ x, float* __restrict__ p)
{
    int idx = blockIdx.x * 256 + threadIdx.x;
    if (idx >= PROWS * DIM) return;
    int kk = idx % DIM, pn = idx / DIM;
    int b = pn / NPATCH, n = pn % NPATCH;
    int c = kk >> 8, ij = kk & 255, i = ij >> 4, j = ij & 15;
    float v = x[((size_t)(b * 3 + c) * 224 + (n / 14) * 16 + i) * 224 + (n % 14) * 16 + j];
    p[(size_t)pn * DIM + permk(kk)] = rna(v);
}
__global__ void cls_embed_kernel(const float* __restrict__ cls, const float* __restrict__ pos,
                                 float* __restrict__ tok)
{
    int idx = blockIdx.x * 256 + threadIdx.x;
    if (idx >= BATCH * DIM) return;
    int b = idx / DIM, d = idx % DIM;
    tok[(size_t)(b * NTOK) * DIM + d] = cls[d] + pos[d];
}

// LayerNorm -> rna + permuted fp32
__global__ void ln_kernel(const float* __restrict__ x, const float* __restrict__ g,
                          const float* __restrict__ b, float* __restrict__ y)
{
    int row = blockIdx.x, tid = threadIdx.x;
    int lane = tid & 31, wd = tid >> 5;
    const float* xr = x + (size_t)row * DIM;
    __shared__ float ws[8], ws2[8];
    float v0 = xr[tid], v1 = xr[tid + 256], v2 = xr[tid + 512];
    float s = v0 + v1 + v2;
    #pragma unroll
    for (int o = 16; o; o >>= 1) s += __shfl_xor_sync(0xffffffffu, s, o);
    if (lane == 0) ws[wd] = s;
    __syncthreads();
    float m = (ws[0] + ws[1] + ws[2] + ws[3] + ws[4] + ws[5] + ws[6] + ws[7]) * (1.0f / DIM);
    float d0 = v0 - m, d1 = v1 - m, d2 = v2 - m;
    float q = d0 * d0 + d1 * d1 + d2 * d2;
    #pragma unroll
    for (int o = 16; o; o >>= 1) q += __shfl_xor_sync(0xffffffffu, q, o);
    if (lane == 0) ws2[wd] = q;
    __syncthreads();
    float var = (ws2[0] + ws2[1] + ws2[2] + ws2[3] + ws2[4] + ws2[5] + ws2[6] + ws2[7]) * (1.0f / DIM);
    float r = rsqrtf(var + 1e-5f);
    float* yr = y + (size_t)row * DIM;
    yr[permk(tid)]       = rna(d0 * r * g[tid]       + b[tid]);
    yr[permk(tid + 256)] = rna(d1 * r * g[tid + 256] + b[tid + 256]);
    yr[permk(tid + 512)] = rna(d2 * r * g[tid + 512] + b[tid + 512]);
}

// ------------------------------------------------------------
// attention (fp32, f32x2): block per (b,h), 8 q per warp
// ------------------------------------------------------------
#define KV_PAD 66
#define SCP 208
#define QS_OFF (2*NTOK*KV_PAD)
#define SC_OFF (QS_OFF + 8*8*HDIM)
#define ATTN_SMEM ((SC_OFF + 8*8*SCP) * (int)sizeof(float))

__global__ void attn_kernel(const float* __restrict__ qkv, float* __restrict__ outp)
{
    int b = blockIdx.x / NHEAD, h = blockIdx.x % NHEAD;
    extern __shared__ float sm[];
    float* Ks = sm;
    float* Vs = Ks + NTOK * KV_PAD;
    const float* base = qkv + (size_t)(b * NTOK) * (3 * DIM) + h * HDIM;
    int tid = threadIdx.x;

    for (int idx = tid; idx < NTOK * HDIM; idx += 256) {
        int t = idx >> 6, d = idx & 63;
        Ks[t * KV_PAD + d] = base[(size_t)t * (3 * DIM) + DIM + d];
        Vs[t * KV_PAD + d] = base[(size_t)t * (3 * DIM) + 2 * DIM + d];
    }
    __syncthreads();

    int w = tid >> 5, lane = tid & 31;
    float* Qw = sm + QS_OFF + w * 8 * HDIM;
    float* Sw = sm + SC_OFF + w * 8 * SCP;
    const int pc0 = permk(h * HDIM + lane);
    const int pc1 = permk(h * HDIM + lane + 32);

    for (int oct = w; oct < 25; oct += 8) {
        int qb = oct * 8;
        for (int idx = lane; idx < 8 * HDIM; idx += 32) {
            int qq = idx >> 6, d = idx & 63;
            int qi = qb + qq; if (qi > NTOK - 1) qi = NTOK - 1;
            Qw[qq * HDIM + d] = base[(size_t)qi * (3 * DIM) + d];
        }
        __syncwarp();
        for (int kt = lane; kt < NTOK; kt += 32) {
            uint64_t s2[8];
            #pragma unroll
            for (int q = 0; q < 8; q++) s2[q] = pack2(0.f, 0.f);
            const float* kr = Ks + kt * KV_PAD;
            #pragma unroll 4
            for (int d = 0; d < HDIM; d += 2) {
                uint64_t k2 = *reinterpret_cast<const uint64_t*>(&kr[d]);
                #pragma unroll
                for (int q = 0; q < 8; q++) {
                    uint64_t q2 = *reinterpret_cast<const uint64_t*>(&Qw[q * HDIM + d]);
                    ffma2(s2[q], q2, k2);
                }
            }
            #pragma unroll
            for (int q = 0; q < 8; q++) {
                float sx, sy;
                unpack2(s2[q], sx, sy);
                Sw[q * SCP + kt] = (sx + sy) * 0.125f;
            }
        }
        __syncwarp();
        float inv[8];
        #pragma unroll
        for (int q = 0; q < 8; q++) {
            float* sq = Sw + q * SCP;
            float mx = -1e30f;
            for (int kt = lane; kt < NTOK; kt += 32) mx = fmaxf(mx, sq[kt]);
            #pragma unroll
            for (int o = 16; o; o >>= 1) mx = fmaxf(mx, __shfl_xor_sync(0xffffffffu, mx, o));
            float su = 0.f;
            for (int kt = lane; kt < NTOK; kt += 32) {
                float e = __expf(sq[kt] - mx);
                sq[kt] = e;
                su += e;
            }
            #pragma unroll
            for (int o = 16; o; o >>= 1) su += __shfl_xor_sync(0xffffffffu, su, o);
            inv[q] = 1.0f / su;
        }
        __syncwarp();
        uint64_t a01[8];
        #pragma unroll
        for (int q = 0; q < 8; q++) a01[q] = pack2(0.f, 0.f);
        for (int kt = 0; kt < NTOK; kt++) {
            float v0 = Vs[kt * KV_PAD + lane];
            float v1 = Vs[kt * KV_PAD + 32 + lane];
            uint64_t vv = pack2(v0, v1);
            #pragma unroll
            for (int q = 0; q < 8; q++) {
                float p = Sw[q * SCP + kt];
                ffma2(a01[q], pack2(p, p), vv);
            }
        }
        #pragma unroll
        for (int q = 0; q < 8; q++) {
            int qi = qb + q;
            if (qi < NTOK) {
                float a0, a1;
                unpack2(a01[q], a0, a1);
                size_t oi = (size_t)(b * NTOK + qi) * DIM;
                outp[oi + pc0] = rna(a0 * inv[q]);
                outp[oi + pc1] = rna(a1 * inv[q]);
            }
        }
        __syncwarp();
    }
}

// ------------------------------------------------------------
// final head
// ------------------------------------------------------------
__global__ void head_kernel(const float* __restrict__ tok,
                            const float* __restrict__ ng, const float* __restrict__ nb,
                            const float* __restrict__ hw, const float* __restrict__ hb,
                            float* __restrict__ out)
{
    int b = blockIdx.x, tid = threadIdx.x;
    const float* xr = tok + (size_t)b * NTOK * DIM;
    __shared__ float red[256];
    __shared__ float yrow[DIM];
    __shared__ float sv;
    float v0 = xr[tid], v1 = xr[tid + 256], v2 = xr[tid + 512];
    red[tid] = v0 + v1 + v2;
    __syncthreads();
    for (int o = 128; o; o >>= 1) { if (tid < o) red[tid] += red[tid + o]; __syncthreads(); }
    if (tid == 0) sv = red[0] * (1.0f / DIM);
    __syncthreads();
    float m = sv;
    float d0 = v0 - m, d1 = v1 - m, d2 = v2 - m;
    red[tid] = d0 * d0 + d1 * d1 + d2 * d2;
    __syncthreads();
    for (int o = 128; o; o >>= 1) { if (tid < o) red[tid] += red[tid + o]; __syncthreads(); }
    if (tid == 0) sv = rsqrtf(red[0] * (1.0f / DIM) + 1e-5f);
    __syncthreads();
    float r = sv;
    yrow[tid]       = d0 * r * ng[tid]       + nb[tid];
    yrow[tid + 256] = d1 * r * ng[tid + 256] + nb[tid + 256];
    yrow[tid + 512] = d2 * r * ng[tid + 512] + nb[tid + 512];
    __syncthreads();
    for (int c = 0; c < 5; c++) {
        float p = 0.f;
        for (int i = tid; i < DIM; i += 256) p = fmaf(yrow[i], hw[i * 5 + c], p);
        red[tid] = p;
        __syncthreads();
        for (int o = 128; o; o >>= 1) { if (tid < o) red[tid] += red[tid + o]; __syncthreads(); }
        if (tid == 0) out[b * 5 + c] = red[0] + hb[c];
        __syncthreads();
    }
}

// ------------------------------------------------------------
// host
// ------------------------------------------------------------
static inline void launch_gemm(const float* A, const float* B, const float* bias,
                               const float* res, float* C, int M, int N, int K, int flags)
{
    dim3 grid(N / 128, (M + 127) / 128);
    if (K == DIM)
        gemm_kernel<24><<<grid, 256, GEMM_SMEM>>>(A, B, bias, res, C, M, N, flags);
    else
        gemm_kernel<96><<<grid, 256, GEMM_SMEM>>>(A, B, bias, res, C, M, N, flags);
}
#define SYMADDR(p, s) cudaGetSymbolAddress((void**)&p, s)

extern "C" void kernel_launch(void* const* d_in, const int* in_sizes, int n_in,
                              void* d_out, int out_size)
{
    const float* x      = (const float*)d_in[0];
    const float* conv_w = (const float*)d_in[1];
    const float* conv_b = (const float*)d_in[2];
    const float* cls_t  = (const float*)d_in[3];
    const float* pos    = (const float*)d_in[4];
    const float* ln1_g  = (const float*)d_in[5];
    const float* ln1_b  = (const float*)d_in[6];
    const float* qkv_w  = (const float*)d_in[7];
    const float* qkv_b  = (const float*)d_in[8];
    const float* proj_w = (const float*)d_in[9];
    const float* proj_b = (const float*)d_in[10];
    const float* ln2_g  = (const float*)d_in[11];
    const float* ln2_b  = (const float*)d_in[12];
    const float* fc1_w  = (const float*)d_in[13];
    const float* fc1_b  = (const float*)d_in[14];
    const float* fc2_w  = (const float*)d_in[15];
    const float* fc2_b  = (const float*)d_in[16];
    const float* norm_g = (const float*)d_in[17];
    const float* norm_b = (const float*)d_in[18];
    const float* head_w = (const float*)d_in[19];
    const float* head_b = (const float*)d_in[20];
    float* out = (float*)d_out;

    float *pA, *cw, *tok, *y, *qkv, *aA, *fA;
    float *qT, *pT, *f1T, *f2T;
    SYMADDR(pA, g_p); SYMADDR(cw, g_cw); SYMADDR(tok, g_tok);
    SYMADDR(y, g_y); SYMADDR(qkv, g_qkv); SYMADDR(aA, g_a); SYMADDR(fA, g_f);
    SYMADDR(qT, g_qkvT); SYMADDR(pT, g_projT); SYMADDR(f1T, g_fc1T); SYMADDR(f2T, g_fc2T);

    cudaFuncSetAttribute(gemm_kernel<24>, cudaFuncAttributeMaxDynamicSharedMemorySize, GEMM_SMEM);
    cudaFuncSetAttribute(gemm_kernel<96>, cudaFuncAttributeMaxDynamicSharedMemorySize, GEMM_SMEM);
    cudaFuncSetAttribute(attn_kernel, cudaFuncAttributeMaxDynamicSharedMemorySize, ATTN_SMEM);

    // launch #4 is the patch GEMM (ncu capture window lands on launch #4)
    im2col_kernel<<<(PROWS * DIM + 255) / 256, 256>>>(x, pA);                          // 1
    roundperm_kernel<<<(DIM * DIM + 255) / 256, 256>>>(conv_w, cw, DIM * DIM);         // 2
    megaA_kernel<<<NLAYER * 2304, dim3(32, 8)>>>(qkv_w, proj_w, qT, pT);               // 3
    launch_gemm(pA, cw, conv_b, pos, tok, PROWS, DIM, DIM, F_BIAS | F_EMB);            // 4
    megaB_kernel<<<NLAYER * 4608, dim3(32, 8)>>>(fc1_w, fc2_w, f1T, f2T);              // 5
    cls_embed_kernel<<<(BATCH * DIM + 255) / 256, 256>>>(cls_t, pos, tok);             // 6

    for (int l = 0; l < NLAYER; l++) {
        ln_kernel<<<ROWS, 256>>>(tok, ln1_g + l * DIM, ln1_b + l * DIM, y);
        launch_gemm(y, qT + (size_t)l * 3 * DIM * DIM, qkv_b + (size_t)l * 3 * DIM,
                    nullptr, qkv, ROWS, 3 * DIM, DIM, F_BIAS);
        attn_kernel<<<BATCH * NHEAD, 256, ATTN_SMEM>>>(qkv, aA);
        launch_gemm(aA, pT + (size_t)l * DIM * DIM, proj_b + (size_t)l * DIM,
                    tok, tok, ROWS, DIM, DIM, F_BIAS | F_RES);
        ln_kernel<<<ROWS, 256>>>(tok, ln2_g + l * DIM, ln2_b + l * DIM, y);
        launch_gemm(y, f1T + (size_t)l * DFF * DIM, fc1_b + (size_t)l * DFF,
                    nullptr, fA, ROWS, DFF, DIM, F_BIAS | F_GELU | F_PERM);
        launch_gemm(fA, f2T + (size_t)l * DIM * DFF, fc2_b + (size_t)l * DIM,
                    tok, tok, ROWS, DIM, DFF, F_BIAS | F_RES);
    }

    head_kernel<<<BATCH, 256>>>(tok, norm_g, norm_b, head_w, head_b, out);
}

// round 17
// speedup vs baseline: 1.1585x; 1.1585x over previous
#include <cuda_runtime.h>
#include <cuda_bf16.h>
#include <cstdint>
#include <math.h>

#define BATCH   32
#define NPATCH  196
#define NTOK    197
#define DIM     768
#define DFF     3072
#define NLAYER  12
#define NHEAD   12
#define HDIM    64
#define ROWS    (BATCH*NTOK)      // 6304
#define PROWS   (BATCH*NPATCH)    // 6272 = 49*128
#define MPAD    6400

// -------- device scratch (fp32 tf32-rounded, k-permuted) --------
__device__ float g_p[PROWS*DIM];
__device__ float g_cw[DIM*DIM];
__device__ float g_tok[ROWS*DIM];
__device__ float g_y[MPAD*DIM];
__device__ float g_qkv[ROWS*3*DIM];
__device__ float g_a[MPAD*DIM];
__device__ float g_f[MPAD*DFF];
__device__ float g_qkvT[NLAYER*3*DIM*DIM];
__device__ float g_projT[NLAYER*DIM*DIM];
__device__ float g_fc1T[(size_t)NLAYER*DFF*DIM];
__device__ float g_fc2T[(size_t)NLAYER*DIM*DFF];

// -------- helpers --------
__device__ __forceinline__ uint32_t smem_u32(const void* p) {
    uint32_t a;
    asm("{ .reg .u64 t; cvta.to.shared.u64 t, %1; cvt.u32.u64 %0, t; }" : "=r"(a) : "l"(p));
    return a;
}
__device__ __forceinline__ float rna(float x) {
    uint32_t u; asm("cvt.rna.tf32.f32 %0, %1;" : "=r"(u) : "f"(x));
    return __uint_as_float(u);
}
__device__ __host__ __forceinline__ int permk(int k) {
    return (k & ~15) | (((k & 3) << 2) | ((k & 15) >> 2));
}
#define CPA16(d, s) asm volatile("cp.async.cg.shared.global [%0], [%1], 16;" :: "r"(d), "l"(s))
#define CP_COMMIT() asm volatile("cp.async.commit_group;" ::: "memory")
#define CP_WAITG2() asm volatile("cp.async.wait_group 2;" ::: "memory")

__device__ __forceinline__ void lds128(uint32_t a, uint32_t* r) {
    asm volatile("ld.shared.v4.b32 {%0,%1,%2,%3}, [%4];"
                 : "=r"(r[0]), "=r"(r[1]), "=r"(r[2]), "=r"(r[3]) : "r"(a));
}
__device__ __forceinline__ void mma_tf32(float* c, uint32_t a0, uint32_t a1, uint32_t a2,
                                         uint32_t a3, uint32_t b0, uint32_t b1) {
    asm volatile("mma.sync.aligned.m16n8k8.row.col.f32.tf32.tf32.f32 "
        "{%0,%1,%2,%3}, {%4,%5,%6,%7}, {%8,%9}, {%0,%1,%2,%3};"
        : "+f"(c[0]), "+f"(c[1]), "+f"(c[2]), "+f"(c[3])
        : "r"(a0), "r"(a1), "r"(a2), "r"(a3), "r"(b0), "r"(b1));
}
__device__ __forceinline__ uint64_t pack2(float x, float y) {
    uint64_t r; asm("mov.b64 %0, {%1,%2};" : "=l"(r) : "f"(x), "f"(y)); return r;
}
__device__ __forceinline__ void unpack2(uint64_t v, float& x, float& y) {
    asm("mov.b64 {%0,%1}, %2;" : "=f"(x), "=f"(y) : "l"(v));
}
__device__ __forceinline__ void ffma2(uint64_t& d, uint64_t a, uint64_t b) {
    asm("fma.rn.f32x2 %0, %1, %2, %0;" : "+l"(d) : "l"(a), "l"(b));
}

// ------------------------------------------------------------
// tf32 GEMM: C = epi(A @ B^T); A[M][permK], B[N][permK] fp32.
// CTA 128x128, warp tile 32x64, k-chunk 16, 4-stage cp.async,
// 64KB smem -> 2 CTAs/SM. NK = K/16 compile-time (48 or 192).
// ------------------------------------------------------------
#define F_BIAS 1
#define F_RES  2
#define F_GELU 4
#define F_PERM 8
#define F_EMB  16

#define ARR_F  8192                    // 128 rows * 64B
#define STAGE_B (2*ARR_F)              // 16384
#define GEMM_SMEM (4*STAGE_B)          // 65536 -> 2 CTAs/SM

template<int NK>
__global__ __launch_bounds__(256, 2) void gemm_kernel(
    const float* __restrict__ A, const float* __restrict__ B,
    const float* __restrict__ bias, const float* __restrict__ res,
    float* __restrict__ Cf, int M, int N, int flags)
{
    constexpr int K = NK * 16;
    extern __shared__ char dsm[];
    const uint32_t sbase = smem_u32(dsm);
    const int tid = threadIdx.x, wid = tid >> 5, lane = tid & 31;
    const int bm = blockIdx.y * 128, bn = blockIdx.x * 128;
    const int warpM = wid & 3, warpN = wid >> 2;

    float acc[64];
    #pragma unroll
    for (int i = 0; i < 64; i++) acc[i] = 0.f;

    auto load_stage = [&](int j) {
        uint32_t sb = sbase + (uint32_t)(j & 3) * STAGE_B;
        int kb = j << 4;
        #pragma unroll
        for (int i = 0; i < 4; i++) {
            int seg = tid + i * 256;
            int mat = seg >> 9, rem = seg & 511;
            int row = rem >> 2, s4 = rem & 3;
            const float* src = (mat ? B + (size_t)(bn + row) * K
                                    : A + (size_t)(bm + row) * K) + kb + s4 * 4;
            uint32_t dst = sb + (uint32_t)mat * ARR_F + (uint32_t)(row * 64 + s4 * 16);
            CPA16(dst, src);
        }
    };

    const int qrow = lane >> 2, qcol = (lane & 3) * 16;

    auto compute_stage = [&](int j) {
        uint32_t sb = sbase + (uint32_t)(j & 3) * STAGE_B;
        uint32_t ax[2][4], ay[2][4], bb[8][4];
        #pragma unroll
        for (int m2 = 0; m2 < 2; m2++) {
            uint32_t r0 = warpM * 32 + m2 * 16 + qrow;
            lds128(sb + r0 * 64 + qcol, ax[m2]);
            lds128(sb + (r0 + 8) * 64 + qcol, ay[m2]);
        }
        #pragma unroll
        for (int p = 0; p < 8; p++) {
            uint32_t nrow = warpN * 64 + p * 8 + qrow;
            lds128(sb + ARR_F + nrow * 64 + qcol, bb[p]);
        }
        #pragma unroll
        for (int m2 = 0; m2 < 2; m2++)
            #pragma unroll
            for (int n8 = 0; n8 < 8; n8++)
                mma_tf32(&acc[(m2 * 8 + n8) * 4],
                         ax[m2][0], ay[m2][0], ax[m2][1], ay[m2][1],
                         bb[n8][0], bb[n8][1]);
        #pragma unroll
        for (int m2 = 0; m2 < 2; m2++)
            #pragma unroll
            for (int n8 = 0; n8 < 8; n8++)
                mma_tf32(&acc[(m2 * 8 + n8) * 4],
                         ax[m2][2], ay[m2][2], ax[m2][3], ay[m2][3],
                         bb[n8][2], bb[n8][3]);
    };

    load_stage(0); CP_COMMIT();
    load_stage(1); CP_COMMIT();
    load_stage(2); CP_COMMIT();
    #pragma unroll 12
    for (int j = 0; j < NK; j++) {
        CP_WAITG2();
        __syncthreads();
        if (j + 3 < NK) load_stage(j + 3);
        CP_COMMIT();
        compute_stage(j);
    }

    // -------- epilogue --------
    #pragma unroll
    for (int m2 = 0; m2 < 2; m2++) {
        #pragma unroll
        for (int n8 = 0; n8 < 8; n8++) {
            float* c = &acc[(m2 * 8 + n8) * 4];
            int row0 = bm + warpM * 32 + m2 * 16 + (lane >> 2);
            int col  = bn + warpN * 64 + n8 * 8 + (lane & 3) * 2;
            #pragma unroll
            for (int h = 0; h < 2; h++) {
                int m = row0 + h * 8;
                if (m >= M) continue;
                float v0 = c[h * 2], v1 = c[h * 2 + 1];
                if (flags & F_BIAS) { v0 += bias[col]; v1 += bias[col + 1]; }
                if (flags & F_GELU) {
                    v0 = 0.5f * v0 * (1.0f + erff(v0 * 0.70710678118654752f));
                    v1 = 0.5f * v1 * (1.0f + erff(v1 * 0.70710678118654752f));
                }
                if (flags & F_EMB) {
                    int bb2 = m / NPATCH, nn = m % NPATCH;
                    float2 pv = *reinterpret_cast<const float2*>(&res[(size_t)(nn + 1) * N + col]);
                    v0 += pv.x; v1 += pv.y;
                    size_t oidx = (size_t)(bb2 * NTOK + nn + 1) * N + col;
                    float2 ov; ov.x = v0; ov.y = v1;
                    *reinterpret_cast<float2*>(&Cf[oidx]) = ov;
                    continue;
                }
                if (flags & F_PERM) {
                    size_t base = (size_t)m * N;
                    Cf[base + permk(col)]     = rna(v0);
                    Cf[base + permk(col + 1)] = rna(v1);
                    continue;
                }
                size_t idx = (size_t)m * N + col;
                if (flags & F_RES) {
                    float2 rv = *reinterpret_cast<const float2*>(&res[idx]);
                    v0 += rv.x; v1 += rv.y;
                }
                float2 ov; ov.x = v0; ov.y = v1;
                *reinterpret_cast<float2*>(&Cf[idx]) = ov;
            }
        }
    }
}

// ------------------------------------------------------------
// weight prep: transpose + rna + permute
// ------------------------------------------------------------
__device__ __forceinline__ void trans_tile(const float* __restrict__ in,
                                           float* __restrict__ outp,
                                           int K, int N, int kt, int nt)
{
    __shared__ float t[32][33];
    int n0 = nt * 32, k0 = kt * 32;
    int tx = threadIdx.x, ty = threadIdx.y;
    #pragma unroll
    for (int i = 0; i < 4; i++)
        t[ty + 8 * i][tx] = in[(size_t)(k0 + ty + 8 * i) * N + n0 + tx];
    __syncthreads();
    #pragma unroll
    for (int i = 0; i < 4; i++)
        outp[(size_t)(n0 + ty + 8 * i) * K + permk(k0 + tx)] = rna(t[tx][ty + 8 * i]);
}

__global__ void megaA_kernel(const float* __restrict__ qkv_w, const float* __restrict__ proj_w,
                             float* __restrict__ qT, float* __restrict__ pT)
{
    int layer = blockIdx.x / 2304, rr = blockIdx.x % 2304;
    if (rr < 1728)
        trans_tile(qkv_w + (size_t)layer * DIM * 3 * DIM,
                   qT + (size_t)layer * 3 * DIM * DIM, DIM, 3 * DIM, rr / 72, rr % 72);
    else {
        int r2 = rr - 1728;
        trans_tile(proj_w + (size_t)layer * DIM * DIM,
                   pT + (size_t)layer * DIM * DIM, DIM, DIM, r2 / 24, r2 % 24);
    }
}
__global__ void megaB_kernel(const float* __restrict__ fc1_w, const float* __restrict__ fc2_w,
                             float* __restrict__ f1T, float* __restrict__ f2T)
{
    int layer = blockIdx.x / 4608, rr = blockIdx.x % 4608;
    if (rr < 2304)
        trans_tile(fc1_w + (size_t)layer * DIM * DFF,
                   f1T + (size_t)layer * DFF * DIM, DIM, DFF, rr / 96, rr % 96);
    else {
        int r2 = rr - 2304;
        trans_tile(fc2_w + (size_t)layer * DFF * DIM,
                   f2T + (size_t)layer * DIM * DFF, DFF, DIM, r2 / 24, r2 % 24);
    }
}

__global__ void roundperm_kernel(const float* __restrict__ in, float* __restrict__ outp, int n)
{
    int idx = blockIdx.x * 256 + threadIdx.x;
    if (idx >= n) return;
    int row = idx / DIM, k = idx % DIM;
    outp[(size_t)row * DIM + permk(k)] = rna(in[idx]);
}
__global__ void im2col_kernel(const float* __restrict__ x, float* __restrict__ p)
{
    int idx = blockIdx.x * 256 + threadIdx.x;
    if (idx >= PROWS * DIM) return;
    int kk = idx % DIM, pn = idx / DIM;
    int b = pn / NPATCH, n = pn % NPATCH;
    int c = kk >> 8, ij = kk & 255, i = ij >> 4, j = ij & 15;
    float v = x[((size_t)(b * 3 + c) * 224 + (n / 14) * 16 + i) * 224 + (n % 14) * 16 + j];
    p[(size_t)pn * DIM + permk(kk)] = rna(v);
}
__global__ void cls_embed_kernel(const float* __restrict__ cls, const float* __restrict__ pos,
                                 float* __restrict__ tok)
{
    int idx = blockIdx.x * 256 + threadIdx.x;
    if (idx >= BATCH * DIM) return;
    int b = idx / DIM, d = idx % DIM;
    tok[(size_t)(b * NTOK) * DIM + d] = cls[d] + pos[d];
}

// LayerNorm -> rna + permuted fp32
__global__ void ln_kernel(const float* __restrict__ x, const float* __restrict__ g,
                          const float* __restrict__ b, float* __restrict__ y)
{
    int row = blockIdx.x, tid = threadIdx.x;
    int lane = tid & 31, wd = tid >> 5;
    const float* xr = x + (size_t)row * DIM;
    __shared__ float ws[8], ws2[8];
    float v0 = xr[tid], v1 = xr[tid + 256], v2 = xr[tid + 512];
    float s = v0 + v1 + v2;
    #pragma unroll
    for (int o = 16; o; o >>= 1) s += __shfl_xor_sync(0xffffffffu, s, o);
    if (lane == 0) ws[wd] = s;
    __syncthreads();
    float m = (ws[0] + ws[1] + ws[2] + ws[3] + ws[4] + ws[5] + ws[6] + ws[7]) * (1.0f / DIM);
    float d0 = v0 - m, d1 = v1 - m, d2 = v2 - m;
    float q = d0 * d0 + d1 * d1 + d2 * d2;
    #pragma unroll
    for (int o = 16; o; o >>= 1) q += __shfl_xor_sync(0xffffffffu, q, o);
    if (lane == 0) ws2[wd] = q;
    __syncthreads();
    float var = (ws2[0] + ws2[1] + ws2[2] + ws2[3] + ws2[4] + ws2[5] + ws2[6] + ws2[7]) * (1.0f / DIM);
    float r = rsqrtf(var + 1e-5f);
    float* yr = y + (size_t)row * DIM;
    yr[permk(tid)]       = rna(d0 * r * g[tid]       + b[tid]);
    yr[permk(tid + 256)] = rna(d1 * r * g[tid + 256] + b[tid + 256]);
    yr[permk(tid + 512)] = rna(d2 * r * g[tid + 512] + b[tid + 512]);
}

// ------------------------------------------------------------
// attention (fp32, f32x2): block per (b,h), 8 q per warp
// ------------------------------------------------------------
#define KV_PAD 66
#define SCP 208
#define QS_OFF (2*NTOK*KV_PAD)
#define SC_OFF (QS_OFF + 8*8*HDIM)
#define ATTN_SMEM ((SC_OFF + 8*8*SCP) * (int)sizeof(float))

__global__ void attn_kernel(const float* __restrict__ qkv, float* __restrict__ outp)
{
    int b = blockIdx.x / NHEAD, h = blockIdx.x % NHEAD;
    extern __shared__ float sm[];
    float* Ks = sm;
    float* Vs = Ks + NTOK * KV_PAD;
    const float* base = qkv + (size_t)(b * NTOK) * (3 * DIM) + h * HDIM;
    int tid = threadIdx.x;

    for (int idx = tid; idx < NTOK * HDIM; idx += 256) {
        int t = idx >> 6, d = idx & 63;
        Ks[t * KV_PAD + d] = base[(size_t)t * (3 * DIM) + DIM + d];
        Vs[t * KV_PAD + d] = base[(size_t)t * (3 * DIM) + 2 * DIM + d];
    }
    __syncthreads();

    int w = tid >> 5, lane = tid & 31;
    float* Qw = sm + QS_OFF + w * 8 * HDIM;
    float* Sw = sm + SC_OFF + w * 8 * SCP;
    const int pc0 = permk(h * HDIM + lane);
    const int pc1 = permk(h * HDIM + lane + 32);

    for (int oct = w; oct < 25; oct += 8) {
        int qb = oct * 8;
        for (int idx = lane; idx < 8 * HDIM; idx += 32) {
            int qq = idx >> 6, d = idx & 63;
            int qi = qb + qq; if (qi > NTOK - 1) qi = NTOK - 1;
            Qw[qq * HDIM + d] = base[(size_t)qi * (3 * DIM) + d];
        }
        __syncwarp();
        for (int kt = lane; kt < NTOK; kt += 32) {
            uint64_t s2[8];
            #pragma unroll
            for (int q = 0; q < 8; q++) s2[q] = pack2(0.f, 0.f);
            const float* kr = Ks + kt * KV_PAD;
            #pragma unroll 4
            for (int d = 0; d < HDIM; d += 2) {
                uint64_t k2 = *reinterpret_cast<const uint64_t*>(&kr[d]);
                #pragma unroll
                for (int q = 0; q < 8; q++) {
                    uint64_t q2 = *reinterpret_cast<const uint64_t*>(&Qw[q * HDIM + d]);
                    ffma2(s2[q], q2, k2);
                }
            }
            #pragma unroll
            for (int q = 0; q < 8; q++) {
                float sx, sy;
                unpack2(s2[q], sx, sy);
                Sw[q * SCP + kt] = (sx + sy) * 0.125f;
            }
        }
        __syncwarp();
        float inv[8];
        #pragma unroll
        for (int q = 0; q < 8; q++) {
            float* sq = Sw + q * SCP;
            float mx = -1e30f;
            for (int kt = lane; kt < NTOK; kt += 32) mx = fmaxf(mx, sq[kt]);
            #pragma unroll
            for (int o = 16; o; o >>= 1) mx = fmaxf(mx, __shfl_xor_sync(0xffffffffu, mx, o));
            float su = 0.f;
            for (int kt = lane; kt < NTOK; kt += 32) {
                float e = __expf(sq[kt] - mx);
                sq[kt] = e;
                su += e;
            }
            #pragma unroll
            for (int o = 16; o; o >>= 1) su += __shfl_xor_sync(0xffffffffu, su, o);
            inv[q] = 1.0f / su;
        }
        __syncwarp();
        uint64_t a01[8];
        #pragma unroll
        for (int q = 0; q < 8; q++) a01[q] = pack2(0.f, 0.f);
        for (int kt = 0; kt < NTOK; kt++) {
            float v0 = Vs[kt * KV_PAD + lane];
            float v1 = Vs[kt * KV_PAD + 32 + lane];
            uint64_t vv = pack2(v0, v1);
            #pragma unroll
            for (int q = 0; q < 8; q++) {
                float p = Sw[q * SCP + kt];
                ffma2(a01[q], pack2(p, p), vv);
            }
        }
        #pragma unroll
        for (int q = 0; q < 8; q++) {
            int qi = qb + q;
            if (qi < NTOK) {
                float a0, a1;
                unpack2(a01[q], a0, a1);
                size_t oi = (size_t)(b * NTOK + qi) * DIM;
                outp[oi + pc0] = rna(a0 * inv[q]);
                outp[oi + pc1] = rna(a1 * inv[q]);
            }
        }
        __syncwarp();
    }
}

// ------------------------------------------------------------
// final head
// ------------------------------------------------------------
__global__ void head_kernel(const float* __restrict__ tok,
                            const float* __restrict__ ng, const float* __restrict__ nb,
                            const float* __restrict__ hw, const float* __restrict__ hb,
                            float* __restrict__ out)
{
    int b = blockIdx.x, tid = threadIdx.x;
    const float* xr = tok + (size_t)b * NTOK * DIM;
    __shared__ float red[256];
    __shared__ float yrow[DIM];
    __shared__ float sv;
    float v0 = xr[tid], v1 = xr[tid + 256], v2 = xr[tid + 512];
    red[tid] = v0 + v1 + v2;
    __syncthreads();
    for (int o = 128; o; o >>= 1) { if (tid < o) red[tid] += red[tid + o]; __syncthreads(); }
    if (tid == 0) sv = red[0] * (1.0f / DIM);
    __syncthreads();
    float m = sv;
    float d0 = v0 - m, d1 = v1 - m, d2 = v2 - m;
    red[tid] = d0 * d0 + d1 * d1 + d2 * d2;
    __syncthreads();
    for (int o = 128; o; o >>= 1) { if (tid < o) red[tid] += red[tid + o]; __syncthreads(); }
    if (tid == 0) sv = rsqrtf(red[0] * (1.0f / DIM) + 1e-5f);
    __syncthreads();
    float r = sv;
    yrow[tid]       = d0 * r * ng[tid]       + nb[tid];
    yrow[tid + 256] = d1 * r * ng[tid + 256] + nb[tid + 256];
    yrow[tid + 512] = d2 * r * ng[tid + 512] + nb[tid + 512];
    __syncthreads();
    for (int c = 0; c < 5; c++) {
        float p = 0.f;
        for (int i = tid; i < DIM; i += 256) p = fmaf(yrow[i], hw[i * 5 + c], p);
        red[tid] = p;
        __syncthreads();
        for (int o = 128; o; o >>= 1) { if (tid < o) red[tid] += red[tid + o]; __syncthreads(); }
        if (tid == 0) out[b * 5 + c] = red[0] + hb[c];
        __syncthreads();
    }
}

// ------------------------------------------------------------
// host
// ------------------------------------------------------------
static inline void launch_gemm(const float* A, const float* B, const float* bias,
                               const float* res, float* C, int M, int N, int K, int flags)
{
    dim3 grid(N / 128, (M + 127) / 128);
    if (K == DIM)
        gemm_kernel<48><<<grid, 256, GEMM_SMEM>>>(A, B, bias, res, C, M, N, flags);
    else
        gemm_kernel<192><<<grid, 256, GEMM_SMEM>>>(A, B, bias, res, C, M, N, flags);
}
#define SYMADDR(p, s) cudaGetSymbolAddress((void**)&p, s)

extern "C" void kernel_launch(void* const* d_in, const int* in_sizes, int n_in,
                              void* d_out, int out_size)
{
    const float* x      = (const float*)d_in[0];
    const float* conv_w = (const float*)d_in[1];
    const float* conv_b = (const float*)d_in[2];
    const float* cls_t  = (const float*)d_in[3];
    const float* pos    = (const float*)d_in[4];
    const float* ln1_g  = (const float*)d_in[5];
    const float* ln1_b  = (const float*)d_in[6];
    const float* qkv_w  = (const float*)d_in[7];
    const float* qkv_b  = (const float*)d_in[8];
    const float* proj_w = (const float*)d_in[9];
    const float* proj_b = (const float*)d_in[10];
    const float* ln2_g  = (const float*)d_in[11];
    const float* ln2_b  = (const float*)d_in[12];
    const float* fc1_w  = (const float*)d_in[13];
    const float* fc1_b  = (const float*)d_in[14];
    const float* fc2_w  = (const float*)d_in[15];
    const float* fc2_b  = (const float*)d_in[16];
    const float* norm_g = (const float*)d_in[17];
    const float* norm_b = (const float*)d_in[18];
    const float* head_w = (const float*)d_in[19];
    const float* head_b = (const float*)d_in[20];
    float* out = (float*)d_out;

    float *pA, *cw, *tok, *y, *qkv, *aA, *fA;
    float *qT, *pT, *f1T, *f2T;
    SYMADDR(pA, g_p); SYMADDR(cw, g_cw); SYMADDR(tok, g_tok);
    SYMADDR(y, g_y); SYMADDR(qkv, g_qkv); SYMADDR(aA, g_a); SYMADDR(fA, g_f);
    SYMADDR(qT, g_qkvT); SYMADDR(pT, g_projT); SYMADDR(f1T, g_fc1T); SYMADDR(f2T, g_fc2T);

    cudaFuncSetAttribute(gemm_kernel<48>,  cudaFuncAttributeMaxDynamicSharedMemorySize, GEMM_SMEM);
    cudaFuncSetAttribute(gemm_kernel<192>, cudaFuncAttributeMaxDynamicSharedMemorySize, GEMM_SMEM);
    cudaFuncSetAttribute(attn_kernel, cudaFuncAttributeMaxDynamicSharedMemorySize, ATTN_SMEM);

    // launch #4 is the patch GEMM (ncu capture window lands on launch #4)
    im2col_kernel<<<(PROWS * DIM + 255) / 256, 256>>>(x, pA);                          // 1
    roundperm_kernel<<<(DIM * DIM + 255) / 256, 256>>>(conv_w, cw, DIM * DIM);         // 2
    megaA_kernel<<<NLAYER * 2304, dim3(32, 8)>>>(qkv_w, proj_w, qT, pT);               // 3
    launch_gemm(pA, cw, conv_b, pos, tok, PROWS, DIM, DIM, F_BIAS | F_EMB);            // 4
    megaB_kernel<<<NLAYER * 4608, dim3(32, 8)>>>(fc1_w, fc2_w, f1T, f2T);              // 5
    cls_embed_kernel<<<(BATCH * DIM + 255) / 256, 256>>>(cls_t, pos, tok);             // 6

    for (int l = 0; l < NLAYER; l++) {
        ln_kernel<<<ROWS, 256>>>(tok, ln1_g + l * DIM, ln1_b + l * DIM, y);
        launch_gemm(y, qT + (size_t)l * 3 * DIM * DIM, qkv_b + (size_t)l * 3 * DIM,
                    nullptr, qkv, ROWS, 3 * DIM, DIM, F_BIAS);
        attn_kernel<<<BATCH * NHEAD, 256, ATTN_SMEM>>>(qkv, aA);
        launch_gemm(aA, pT + (size_t)l * DIM * DIM, proj_b + (size_t)l * DIM,
                    tok, tok, ROWS, DIM, DIM, F_BIAS | F_RES);
        ln_kernel<<<ROWS, 256>>>(tok, ln2_g + l * DIM, ln2_b + l * DIM, y);
        launch_gemm(y, f1T + (size_t)l * DFF * DIM, fc1_b + (size_t)l * DFF,
                    nullptr, fA, ROWS, DFF, DIM, F_BIAS | F_GELU | F_PERM);
        launch_gemm(fA, f2T + (size_t)l * DIM * DFF, fc2_b + (size_t)l * DIM,
                    tok, tok, ROWS, DIM, DFF, F_BIAS | F_RES);
    }

    head_kernel<<<BATCH, 256>>>(tok, norm_g, norm_b, head_w, head_b, out);
}